// round 17
// baseline (speedup 1.0000x reference)
#include <cuda_runtime.h>
#include <cuda_bf16.h>
#include <math.h>
#include <stdint.h>

// Problem constants
#define BATCH 2
#define SEQ   2048
#define DM    1024
#define NH    16
#define DK    64
#define MTOT  (BATCH*SEQ)       // 4096

// ---------------- scratch (no allocations allowed) ----------------
__device__ __nv_bfloat16 g_Ahi[3][MTOT*DM];   // activations hi (q,k,v; [0] reused by attn out)
__device__ __nv_bfloat16 g_Alo[3][MTOT*DM];
__device__ __nv_bfloat16 g_WhT[4][DM*DM];
__device__ __nv_bfloat16 g_WlT[4][DM*DM];
__device__ __nv_bfloat16 g_Qhi[MTOT*DM];
__device__ __nv_bfloat16 g_Qlo[MTOT*DM];
__device__ __nv_bfloat16 g_Khi[MTOT*DM];
__device__ __nv_bfloat16 g_Klo[MTOT*DM];
__device__ __nv_bfloat16 g_Vhi[MTOT*DM];
__device__ __nv_bfloat16 g_Vlo[MTOT*DM];
__device__ uint64_t      g_Mpk[BATCH*SEQ*(SEQ/64)];   // bit-packed mask, 1MB

__device__ __forceinline__ uint32_t smem_u32(const void* p) {
    uint32_t a;
    asm("{ .reg .u64 t; cvta.to.shared.u64 t, %1; cvt.u32.u64 %0, t; }"
        : "=r"(a) : "l"(p));
    return a;
}

#define CP16(dst_u32, src_ptr) \
    asm volatile("cp.async.ca.shared.global [%0], [%1], 16;" \
                 :: "r"(dst_u32), "l"((uint64_t)__cvta_generic_to_global(src_ptr)) : "memory")
#define CP_COMMIT() asm volatile("cp.async.commit_group;" ::: "memory")
#define CP_WAIT1()  asm volatile("cp.async.wait_group 1;" ::: "memory")
#define CP_WAIT0()  asm volatile("cp.async.wait_group 0;" ::: "memory")

#define LDSM4(r0, r1, r2, r3, addr) \
    asm volatile("ldmatrix.sync.aligned.m8n8.x4.shared.b16 {%0,%1,%2,%3}, [%4];" \
                 : "=r"(r0), "=r"(r1), "=r"(r2), "=r"(r3) : "r"(addr))

__device__ __forceinline__ void split2(float a, float b, uint32_t& hi, uint32_t& lo) {
    __nv_bfloat162 h = __float22bfloat162_rn(make_float2(a, b));
    float2 hf = __bfloat1622float2(h);
    __nv_bfloat162 l = __float22bfloat162_rn(make_float2(a - hf.x, b - hf.y));
    hi = *(uint32_t*)&h;
    lo = *(uint32_t*)&l;
}

__device__ __forceinline__ void mma16816(float* c, const uint32_t* a, const uint32_t* b) {
    asm volatile(
        "mma.sync.aligned.m16n8k16.row.col.f32.bf16.bf16.f32 "
        "{%0,%1,%2,%3},{%4,%5,%6,%7},{%8,%9},{%0,%1,%2,%3};"
        : "+f"(c[0]), "+f"(c[1]), "+f"(c[2]), "+f"(c[3])
        : "r"(a[0]), "r"(a[1]), "r"(a[2]), "r"(a[3]), "r"(b[0]), "r"(b[1]));
}

// ---------------- pre-passes (merged) ----------------
__global__ __launch_bounds__(256)
void conv_act3(const float* __restrict__ q, const float* __restrict__ k,
               const float* __restrict__ v,
               __nv_bfloat16* __restrict__ Ahi, __nv_bfloat16* __restrict__ Alo)
{
    const int z = blockIdx.z;
    const float* X = (z == 0) ? q : (z == 1) ? k : v;
    size_t idx = blockIdx.x * 256 + threadIdx.x;
    float4 x = ((const float4*)X)[idx];
    uint32_t h0, l0, h1, l1;
    split2(x.x, x.y, h0, l0);
    split2(x.z, x.w, h1, l1);
    ((uint2*)(Ahi + (size_t)z * MTOT * DM))[idx] = make_uint2(h0, h1);
    ((uint2*)(Alo + (size_t)z * MTOT * DM))[idx] = make_uint2(l0, l1);
}

__global__ __launch_bounds__(256)
void conv_w4(const float* __restrict__ w0, const float* __restrict__ w1,
             const float* __restrict__ w2, const float* __restrict__ w3,
             __nv_bfloat16* __restrict__ WhT, __nv_bfloat16* __restrict__ WlT)
{
    __shared__ float ts[32][33];
    const int z = blockIdx.z;
    const float* W = (z == 0) ? w0 : (z == 1) ? w1 : (z == 2) ? w2 : w3;
    __nv_bfloat16* Wh = WhT + (size_t)z * DM * DM;
    __nv_bfloat16* Wl = WlT + (size_t)z * DM * DM;
    const int tx = threadIdx.x, ty = threadIdx.y;   // (32, 8)
    const int kt = blockIdx.y * 32, nt = blockIdx.x * 32;
#pragma unroll
    for (int i = 0; i < 4; i++)
        ts[ty + 8 * i][tx] = W[(size_t)(kt + ty + 8 * i) * DM + nt + tx];
    __syncthreads();
#pragma unroll
    for (int i = 0; i < 4; i++) {
        int n = nt + ty + 8 * i;
        int k = kt + tx;
        float v = ts[tx][ty + 8 * i];
        __nv_bfloat16 h = __float2bfloat16(v);
        __nv_bfloat16 l = __float2bfloat16(v - __bfloat162float(h));
        Wh[(size_t)n * DM + k] = h;
        Wl[(size_t)n * DM + k] = l;
    }
}

__global__ __launch_bounds__(256)
void pack_mask(const int* __restrict__ mask, uint64_t* __restrict__ Mpk)
{
    int idx = blockIdx.x * 256 + threadIdx.x;
    const int4* src = (const int4*)mask + (size_t)idx * 16;
    uint64_t w = 0;
#pragma unroll
    for (int i = 0; i < 16; i++) {
        int4 v = src[i];
        uint64_t nib = (uint64_t)((v.x != 0) | ((v.y != 0) << 1) |
                                  ((v.z != 0) << 2) | ((v.w != 0) << 3));
        w |= nib << (i * 4);
    }
    Mpk[idx] = w;
}

// ==================== HMMA bf16 GEMM (pass-fused, CTA 128x256, warp 64x64) ====================
#define BSTR  40
#define ATB   (128 * BSTR * 2)     // 10240 B: A tile (128 x 32 halves)
#define BTB   (256 * BSTR * 2)     // 20480 B: B tile (256 x 32 halves)
#define STG2  (2 * ATB + 2 * BTB)  // 61440: Ahi, Alo, Bhi, Blo
#define SMEM_GEMM (2 * STG2)       // 122880

__global__ __launch_bounds__(256, 1)
void tc_gemm(const __nv_bfloat16* __restrict__ Xhi, const __nv_bfloat16* __restrict__ Xlo,
             const __nv_bfloat16* __restrict__ WhT, const __nv_bfloat16* __restrict__ WlT,
             const float* __restrict__ bias, float* __restrict__ Yf,
             __nv_bfloat16* __restrict__ Yh, __nv_bfloat16* __restrict__ Yl, int mode)
{
    extern __shared__ char sm[];
    const int tid  = threadIdx.x;
    const int wid  = tid >> 5;
    const int lane = tid & 31;
    const int wm   = wid >> 2;       // 0..1  (M)
    const int wn   = wid & 3;        // 0..3  (N)
    const int bm   = blockIdx.y * 128;
    const int bn   = blockIdx.x * 256;
    const uint32_t sb = smem_u32(sm);

    // staging: A rows 128 (2 threads/row), B rows 256 (1 thread/row)
    const int arow = tid >> 1;
    const int acolh = (tid & 1) * 16;
    const uint32_t sdA = sb + (uint32_t)(arow * BSTR + acolh) * 2;
    const uint32_t sdB = sb + 2 * ATB + (uint32_t)(tid * BSTR) * 2;

    const __nv_bfloat16* Ah_src = Xhi + (size_t)(bm + arow) * DM + acolh;
    const __nv_bfloat16* Al_src = Xlo + (size_t)(bm + arow) * DM + acolh;
    const __nv_bfloat16* Bh_src = WhT + (size_t)(bn + tid) * DM;
    const __nv_bfloat16* Bl_src = WlT + (size_t)(bn + tid) * DM;

    auto stage = [&](int buf, int blk) {
        const int k0 = blk * 32;
        const uint32_t dA = sdA + buf * STG2;
        const uint32_t dB = sdB + buf * STG2;
        CP16(dA,            Ah_src + k0);  CP16(dA + 16,           Ah_src + k0 + 8);
        CP16(dA + ATB,      Al_src + k0);  CP16(dA + ATB + 16,     Al_src + k0 + 8);
#pragma unroll
        for (int i = 0; i < 4; i++) {
            CP16(dB + i * 16,       Bh_src + k0 + i * 8);
            CP16(dB + BTB + i * 16, Bl_src + k0 + i * 8);
        }
    };

    // ldmatrix per-lane offsets (halves) within a tile
    const int aoff0 = (wm * 64 + ((lane >> 3) & 1) * 8 + (lane & 7)) * BSTR + (lane >> 4) * 8;
    const int boff0 = (wn * 64 + (lane >> 4) * 8 + (lane & 7)) * BSTR + ((lane >> 3) & 1) * 8;

    float acc[4][8][4];
#pragma unroll
    for (int i = 0; i < 4; i++)
#pragma unroll
        for (int j = 0; j < 8; j++)
#pragma unroll
            for (int r = 0; r < 4; r++) acc[i][j][r] = 0.f;

    stage(0, 0);
    CP_COMMIT();

    const int r4 = lane >> 2;
    const int c4 = (lane & 3) * 2;

    for (int it = 0; it < 32; it++) {
        const int cur = it & 1;
        if (it + 1 < 32) stage(cur ^ 1, it + 1);
        CP_COMMIT();
        CP_WAIT1();
        __syncthreads();

        const uint32_t AhB = sb + cur * STG2 + aoff0 * 2;
        const uint32_t AlB = AhB + ATB;
        const uint32_t BhB = sb + cur * STG2 + 2 * ATB + boff0 * 2;
        const uint32_t BlB = BhB + BTB;

#pragma unroll
        for (int ks = 0; ks < 2; ks++) {
            const uint32_t ko = (uint32_t)(ks * 16) * 2;
            uint32_t ah[4][4], al[4][4];
#pragma unroll
            for (int mt = 0; mt < 4; mt++) {
                const uint32_t mo = (uint32_t)(mt * 16 * BSTR) * 2 + ko;
                LDSM4(ah[mt][0], ah[mt][1], ah[mt][2], ah[mt][3], AhB + mo);
                LDSM4(al[mt][0], al[mt][1], al[mt][2], al[mt][3], AlB + mo);
            }
            {
                uint32_t bh[8][2];
#pragma unroll
                for (int np = 0; np < 4; np++)
                    LDSM4(bh[2 * np][0], bh[2 * np][1], bh[2 * np + 1][0], bh[2 * np + 1][1],
                          BhB + (uint32_t)(np * 16 * BSTR) * 2 + ko);
#pragma unroll
                for (int mt = 0; mt < 4; mt++)
#pragma unroll
                    for (int nt = 0; nt < 8; nt++)
                        mma16816(acc[mt][nt], ah[mt], bh[nt]);
#pragma unroll
                for (int mt = 0; mt < 4; mt++)
#pragma unroll
                    for (int nt = 0; nt < 8; nt++)
                        mma16816(acc[mt][nt], al[mt], bh[nt]);
            }
            {
                uint32_t bl[8][2];
#pragma unroll
                for (int np = 0; np < 4; np++)
                    LDSM4(bl[2 * np][0], bl[2 * np][1], bl[2 * np + 1][0], bl[2 * np + 1][1],
                          BlB + (uint32_t)(np * 16 * BSTR) * 2 + ko);
#pragma unroll
                for (int mt = 0; mt < 4; mt++)
#pragma unroll
                    for (int nt = 0; nt < 8; nt++)
                        mma16816(acc[mt][nt], ah[mt], bl[nt]);
            }
        }
        __syncthreads();
    }

    // ---------------- epilogue ----------------
#pragma unroll
    for (int mt = 0; mt < 4; mt++) {
#pragma unroll
        for (int rr = 0; rr < 2; rr++) {
            const int m  = bm + wm * 64 + mt * 16 + r4 + rr * 8;
            const int bq = m >> 11, sq = m & (SEQ - 1);
#pragma unroll
            for (int nt = 0; nt < 8; nt++) {
                const int n = bn + wn * 64 + nt * 8 + c4;
                float v0 = acc[mt][nt][rr * 2], v1 = acc[mt][nt][rr * 2 + 1];
                if (bias) { v0 += bias[n]; v1 += bias[n + 1]; }
                if (mode == 1) { v0 *= 0.125f; v1 *= 0.125f; }
                if (mode == 0) {
                    *(float2*)&Yf[(size_t)m * DM + n] = make_float2(v0, v1);
                } else if (mode == 3) {
                    const int hh = n >> 6, dk = n & 63;
                    size_t i0 = ((size_t)(bq * NH + hh) * DK + dk) * SEQ + sq;
                    __nv_bfloat16 h0 = __float2bfloat16(v0);
                    __nv_bfloat16 h1 = __float2bfloat16(v1);
                    Yh[i0]       = h0;
                    Yh[i0 + SEQ] = h1;
                    Yl[i0]       = __float2bfloat16(v0 - __bfloat162float(h0));
                    Yl[i0 + SEQ] = __float2bfloat16(v1 - __bfloat162float(h1));
                } else {
                    uint32_t hi, lo;
                    split2(v0, v1, hi, lo);
                    const int hh = n >> 6, dk = n & 63;
                    size_t idx = ((size_t)(bq * NH + hh) * SEQ + sq) * DK + dk;
                    *(uint32_t*)&Yh[idx] = hi;
                    *(uint32_t*)&Yl[idx] = lo;
                }
            }
        }
    }
}

// ==================== HMMA flash attention (unchanged from R15) ====================
#define ATSTR 72
#define ATILE (64 * ATSTR * 2)    // 9216 B
#define ASTAGE (4 * ATILE)        // 36864: Khi, Klo, Vhi, Vlo
#define QTILE (128 * ATSTR * 2)   // 18432
#define SMEM_ATT (2 * ASTAGE)     // 73728

__global__ __launch_bounds__(256, 2)
void attn_tc(const __nv_bfloat16* __restrict__ Qhi_, const __nv_bfloat16* __restrict__ Qlo_,
             const __nv_bfloat16* __restrict__ Khi_, const __nv_bfloat16* __restrict__ Klo_,
             const __nv_bfloat16* __restrict__ Vhi_, const __nv_bfloat16* __restrict__ Vlo_,
             const uint64_t* __restrict__ Mpk,
             __nv_bfloat16* __restrict__ Ohi, __nv_bfloat16* __restrict__ Olo)
{
    extern __shared__ char sm[];
    const int tid  = threadIdx.x;
    const int wid  = tid >> 5;
    const int lane = tid & 31;
    const int r4   = lane >> 2;
    const int c4   = (lane & 3) * 2;
    const int qt   = blockIdx.x;
    const int bh   = blockIdx.y;
    const int b    = bh >> 4;
    const int h    = bh & 15;
    const uint32_t sb = smem_u32(sm);

#pragma unroll
    for (int i = 0; i < 4; i++) {
        int c    = tid + i * 256;
        int qrow = c >> 3;
        int off  = (c & 7) * 8;
        const __nv_bfloat16* s0 = Qhi_ + ((size_t)bh * SEQ + qt * 128 + qrow) * DK + off;
        const __nv_bfloat16* s1 = Qlo_ + ((size_t)bh * SEQ + qt * 128 + qrow) * DK + off;
        uint32_t d = sb + (uint32_t)(qrow * ATSTR + off) * 2;
        CP16(d, s0);
        CP16(d + QTILE, s1);
    }
    CP_COMMIT();
    CP_WAIT0();
    __syncthreads();

    uint32_t qh[4][4], ql[4][4];
    {
        const uint32_t qoff = (uint32_t)((wid * 16 + ((lane >> 3) & 1) * 8 + (lane & 7)) * ATSTR
                                          + (lane >> 4) * 8) * 2;
#pragma unroll
        for (int ks = 0; ks < 4; ks++) {
            LDSM4(qh[ks][0], qh[ks][1], qh[ks][2], qh[ks][3], sb + qoff + ks * 32);
            LDSM4(ql[ks][0], ql[ks][1], ql[ks][2], ql[ks][3], sb + QTILE + qoff + ks * 32);
        }
    }
    __syncthreads();

    auto stageKV = [&](int buf, int kt) {
        const int krow = tid >> 2;
        const int off  = (tid & 3) * 16;
        uint32_t d = sb + buf * ASTAGE + (uint32_t)(krow * ATSTR + off) * 2;
        const __nv_bfloat16* k0 = Khi_ + ((size_t)bh * SEQ + kt * 64 + krow) * DK + off;
        const __nv_bfloat16* k1 = Klo_ + ((size_t)bh * SEQ + kt * 64 + krow) * DK + off;
        const __nv_bfloat16* v0 = Vhi_ + ((size_t)bh * DK + krow) * SEQ + kt * 64 + off;
        const __nv_bfloat16* v1 = Vlo_ + ((size_t)bh * DK + krow) * SEQ + kt * 64 + off;
        CP16(d,                  k0);     CP16(d + 16,              k0 + 8);
        CP16(d + ATILE,          k1);     CP16(d + ATILE + 16,      k1 + 8);
        CP16(d + 2 * ATILE,      v0);     CP16(d + 2 * ATILE + 16,  v0 + 8);
        CP16(d + 3 * ATILE,      v1);     CP16(d + 3 * ATILE + 16,  v1 + 8);
    };

    stageKV(0, 0);
    CP_COMMIT();

    float oacc[8][4];
#pragma unroll
    for (int nb = 0; nb < 8; nb++)
#pragma unroll
        for (int r = 0; r < 4; r++) oacc[nb][r] = 0.f;
    float mrun0 = -1e30f, mrun1 = -1e30f, lrun0 = 0.f, lrun1 = 0.f;

    const int ro0 = qt * 128 + wid * 16 + r4;
    const uint64_t* mrow0 = Mpk + ((size_t)b * SEQ + ro0) * (SEQ / 64);
    const uint64_t* mrow1 = mrow0 + 8 * (SEQ / 64);

    const uint32_t kvoff = (uint32_t)(((lane >> 4) * 8 + (lane & 7)) * ATSTR
                                       + ((lane >> 3) & 1) * 8) * 2;

    for (int kt = 0; kt < 32; kt++) {
        const int cur = kt & 1;
        const uint64_t w0 = mrow0[kt];
        const uint64_t w1 = mrow1[kt];

        if (kt + 1 < 32) { stageKV(cur ^ 1, kt + 1); CP_COMMIT(); CP_WAIT1(); }
        else             { CP_WAIT0(); }
        __syncthreads();

        const uint32_t KhB = sb + cur * ASTAGE + kvoff;
        const uint32_t KlB = KhB + ATILE;
        const uint32_t VhB = KhB + 2 * ATILE;
        const uint32_t VlB = KhB + 3 * ATILE;

        float sacc[8][4];
#pragma unroll
        for (int nb = 0; nb < 8; nb++)
#pragma unroll
            for (int r = 0; r < 4; r++) sacc[nb][r] = 0.f;

#pragma unroll
        for (int ks = 0; ks < 4; ks++) {
            {
                uint32_t kh2[8][2];
#pragma unroll
                for (int np = 0; np < 4; np++) {
                    const uint32_t o = (uint32_t)(np * 16 * ATSTR) * 2 + ks * 32;
                    LDSM4(kh2[2 * np][0], kh2[2 * np][1], kh2[2 * np + 1][0],
                          kh2[2 * np + 1][1], KhB + o);
                }
#pragma unroll
                for (int nb = 0; nb < 8; nb++) mma16816(sacc[nb], qh[ks], kh2[nb]);
#pragma unroll
                for (int nb = 0; nb < 8; nb++) mma16816(sacc[nb], ql[ks], kh2[nb]);
            }
            {
                uint32_t kl2[8][2];
#pragma unroll
                for (int np = 0; np < 4; np++) {
                    const uint32_t o = (uint32_t)(np * 16 * ATSTR) * 2 + ks * 32;
                    LDSM4(kl2[2 * np][0], kl2[2 * np][1], kl2[2 * np + 1][0],
                          kl2[2 * np + 1][1], KlB + o);
                }
#pragma unroll
                for (int nb = 0; nb < 8; nb++) mma16816(sacc[nb], qh[ks], kl2[nb]);
            }
        }

#pragma unroll
        for (int nb = 0; nb < 8; nb++) {
            const int j = nb * 8 + c4;
            if (!((w0 >> j) & 1))       sacc[nb][0] = -1e30f;
            if (!((w0 >> (j + 1)) & 1)) sacc[nb][1] = -1e30f;
            if (!((w1 >> j) & 1))       sacc[nb][2] = -1e30f;
            if (!((w1 >> (j + 1)) & 1)) sacc[nb][3] = -1e30f;
        }

        float mx0 = -1e30f, mx1 = -1e30f;
#pragma unroll
        for (int nb = 0; nb < 8; nb++) {
            mx0 = fmaxf(mx0, fmaxf(sacc[nb][0], sacc[nb][1]));
            mx1 = fmaxf(mx1, fmaxf(sacc[nb][2], sacc[nb][3]));
        }
        mx0 = fmaxf(mx0, __shfl_xor_sync(0xffffffffu, mx0, 1));
        mx0 = fmaxf(mx0, __shfl_xor_sync(0xffffffffu, mx0, 2));
        mx1 = fmaxf(mx1, __shfl_xor_sync(0xffffffffu, mx1, 1));
        mx1 = fmaxf(mx1, __shfl_xor_sync(0xffffffffu, mx1, 2));

        const float mn0 = fmaxf(mrun0, mx0);
        const float mn1 = fmaxf(mrun1, mx1);
        const float scl0 = __expf(mrun0 - mn0);
        const float scl1 = __expf(mrun1 - mn1);
        mrun0 = mn0; mrun1 = mn1;

        float rs0 = 0.f, rs1 = 0.f;
#pragma unroll
        for (int nb = 0; nb < 8; nb++) {
            sacc[nb][0] = __expf(sacc[nb][0] - mn0);
            sacc[nb][1] = __expf(sacc[nb][1] - mn0);
            sacc[nb][2] = __expf(sacc[nb][2] - mn1);
            sacc[nb][3] = __expf(sacc[nb][3] - mn1);
            rs0 += sacc[nb][0] + sacc[nb][1];
            rs1 += sacc[nb][2] + sacc[nb][3];
        }
        rs0 += __shfl_xor_sync(0xffffffffu, rs0, 1);
        rs0 += __shfl_xor_sync(0xffffffffu, rs0, 2);
        rs1 += __shfl_xor_sync(0xffffffffu, rs1, 1);
        rs1 += __shfl_xor_sync(0xffffffffu, rs1, 2);
        lrun0 = lrun0 * scl0 + rs0;
        lrun1 = lrun1 * scl1 + rs1;

#pragma unroll
        for (int nb = 0; nb < 8; nb++) {
            oacc[nb][0] *= scl0; oacc[nb][1] *= scl0;
            oacc[nb][2] *= scl1; oacc[nb][3] *= scl1;
        }

        uint32_t pah[4][4], pal[4][4];
#pragma unroll
        for (int ks = 0; ks < 4; ks++) {
            split2(sacc[2 * ks][0],     sacc[2 * ks][1],     pah[ks][0], pal[ks][0]);
            split2(sacc[2 * ks][2],     sacc[2 * ks][3],     pah[ks][1], pal[ks][1]);
            split2(sacc[2 * ks + 1][0], sacc[2 * ks + 1][1], pah[ks][2], pal[ks][2]);
            split2(sacc[2 * ks + 1][2], sacc[2 * ks + 1][3], pah[ks][3], pal[ks][3]);
        }

#pragma unroll
        for (int ks = 0; ks < 4; ks++) {
            {
                uint32_t vh2[8][2];
#pragma unroll
                for (int np = 0; np < 4; np++) {
                    const uint32_t o = (uint32_t)(np * 16 * ATSTR) * 2 + ks * 32;
                    LDSM4(vh2[2 * np][0], vh2[2 * np][1], vh2[2 * np + 1][0],
                          vh2[2 * np + 1][1], VhB + o);
                }
#pragma unroll
                for (int nb = 0; nb < 8; nb++) mma16816(oacc[nb], pah[ks], vh2[nb]);
#pragma unroll
                for (int nb = 0; nb < 8; nb++) mma16816(oacc[nb], pal[ks], vh2[nb]);
            }
            {
                uint32_t vl2[8][2];
#pragma unroll
                for (int np = 0; np < 4; np++) {
                    const uint32_t o = (uint32_t)(np * 16 * ATSTR) * 2 + ks * 32;
                    LDSM4(vl2[2 * np][0], vl2[2 * np][1], vl2[2 * np + 1][0],
                          vl2[2 * np + 1][1], VlB + o);
                }
#pragma unroll
                for (int nb = 0; nb < 8; nb++) mma16816(oacc[nb], pah[ks], vl2[nb]);
            }
        }
        __syncthreads();
    }

    const float inv0 = (lrun0 > 0.f) ? 1.f / lrun0 : 0.f;
    const float inv1 = (lrun1 > 0.f) ? 1.f / lrun1 : 0.f;
    const size_t m0 = (size_t)b * SEQ + ro0;
#pragma unroll
    for (int nb = 0; nb < 8; nb++) {
        const int col = h * DK + nb * 8 + c4;
        uint32_t hi, lo;
        split2(oacc[nb][0] * inv0, oacc[nb][1] * inv0, hi, lo);
        *(uint32_t*)&Ohi[m0 * DM + col] = hi;
        *(uint32_t*)&Olo[m0 * DM + col] = lo;
        split2(oacc[nb][2] * inv1, oacc[nb][3] * inv1, hi, lo);
        *(uint32_t*)&Ohi[(m0 + 8) * DM + col] = hi;
        *(uint32_t*)&Olo[(m0 + 8) * DM + col] = lo;
    }
}

// ---------------- launch ----------------
extern "C" void kernel_launch(void* const* d_in, const int* in_sizes, int n_in,
                              void* d_out, int out_size)
{
    const float* q    = (const float*)d_in[0];
    const float* k    = (const float*)d_in[1];
    const float* v    = (const float*)d_in[2];
    const int*   mask = (const int*)  d_in[3];
    const float* wq   = (const float*)d_in[4];
    const float* bq   = (const float*)d_in[5];
    const float* wk   = (const float*)d_in[6];
    const float* wv   = (const float*)d_in[7];
    const float* bv   = (const float*)d_in[8];
    const float* wf   = (const float*)d_in[9];
    const float* bf   = (const float*)d_in[10];
    float* out = (float*)d_out;

    __nv_bfloat16 *Ahi, *Alo, *WhT, *WlT, *Qhi, *Qlo, *Khi, *Klo, *Vhi, *Vlo;
    uint64_t* Mpk;
    cudaGetSymbolAddress((void**)&Ahi, g_Ahi);
    cudaGetSymbolAddress((void**)&Alo, g_Alo);
    cudaGetSymbolAddress((void**)&WhT, g_WhT);
    cudaGetSymbolAddress((void**)&WlT, g_WlT);
    cudaGetSymbolAddress((void**)&Qhi, g_Qhi);
    cudaGetSymbolAddress((void**)&Qlo, g_Qlo);
    cudaGetSymbolAddress((void**)&Khi, g_Khi);
    cudaGetSymbolAddress((void**)&Klo, g_Klo);
    cudaGetSymbolAddress((void**)&Vhi, g_Vhi);
    cudaGetSymbolAddress((void**)&Vlo, g_Vlo);
    cudaGetSymbolAddress((void**)&Mpk, g_Mpk);

    cudaFuncSetAttribute(tc_gemm,
                         cudaFuncAttributeMaxDynamicSharedMemorySize, SMEM_GEMM);
    cudaFuncSetAttribute(attn_tc,
                         cudaFuncAttributeMaxDynamicSharedMemorySize, SMEM_ATT);

    // merged pre-passes
    pack_mask<<<(BATCH * SEQ * (SEQ / 64)) / 256, 256>>>(mask, Mpk);
    conv_w4<<<dim3(32, 32, 4), dim3(32, 8)>>>(wq, wk, wv, wf, WhT, WlT);
    conv_act3<<<dim3(MTOT * DM / 1024, 1, 3), 256>>>(q, k, v, Ahi, Alo);

    dim3 ggrid(DM / 256, MTOT / 128);   // (4, 32) = 128 CTAs, 1 wave

    tc_gemm<<<ggrid, 256, SMEM_GEMM>>>(Ahi + 0 * (size_t)MTOT * DM, Alo + 0 * (size_t)MTOT * DM,
                                       WhT + 0 * DM * DM, WlT + 0 * DM * DM,
                                       bq, nullptr, Qhi, Qlo, 1);
    tc_gemm<<<ggrid, 256, SMEM_GEMM>>>(Ahi + 1 * (size_t)MTOT * DM, Alo + 1 * (size_t)MTOT * DM,
                                       WhT + 1 * DM * DM, WlT + 1 * DM * DM,
                                       nullptr, nullptr, Khi, Klo, 2);
    tc_gemm<<<ggrid, 256, SMEM_GEMM>>>(Ahi + 2 * (size_t)MTOT * DM, Alo + 2 * (size_t)MTOT * DM,
                                       WhT + 2 * DM * DM, WlT + 2 * DM * DM,
                                       bv, nullptr, Vhi, Vlo, 3);

    attn_tc<<<dim3(SEQ / 128, BATCH * NH), 256, SMEM_ATT>>>(Qhi, Qlo, Khi, Klo,
                                                            Vhi, Vlo, Mpk, Ahi, Alo);

    tc_gemm<<<ggrid, 256, SMEM_GEMM>>>(Ahi, Alo,
                                       WhT + 3 * DM * DM, WlT + 3 * DM * DM,
                                       bf, out, nullptr, nullptr, 0);
}